// round 6
// baseline (speedup 1.0000x reference)
#include <cuda_runtime.h>
#include <math.h>

#define NPIX  (512*1024)
#define NB    8
#define KBINS 16
#define CBINS 4
#define NACC  (KBINS*CBINS + CBINS)   // 64 p_cl + 4 p_l = 68
#define TPB   128
#define BPSM  6
#define GRID  (148 * BPSM)            // one wave at <=85 regs

__device__ float g_acc[NACC];         // zero at module load; reset by last block each run
__device__ unsigned int g_ticket;     // zero at module load; reset by last block each run

__device__ __forceinline__ float tanh_fast(float x) {
    float r;
    asm("tanh.approx.f32 %0, %1;" : "=f"(r) : "f"(x));
    return r;
}

__global__ void __launch_bounds__(TPB, BPSM)
nid_kernel(const float* __restrict__ cam, const float* __restrict__ lab,
           float* __restrict__ out)
{
    float acc_cl[KBINS * CBINS];
    float acc_l[CBINS];
#pragma unroll
    for (int i = 0; i < KBINS * CBINS; i++) acc_cl[i] = 0.0f;
#pragma unroll
    for (int c = 0; c < CBINS; c++) acc_l[c] = 0.0f;

    const int stride = GRID * TPB;
#pragma unroll 1
    for (int n = blockIdx.x * TPB + threadIdx.x; n < NPIX; n += stride) {
        // T[k] = sum_b tanh(100*gray_b - 6.25*k)  (edge sigmoids, halved arg;
        // the +1 and *0.5 of sigmoid cancel in differences / normalization)
        float T[KBINS + 1];
        float PlS[CBINS];
#pragma unroll
        for (int k = 0; k <= KBINS; k++) T[k] = 0.0f;
#pragma unroll
        for (int c = 0; c < CBINS; c++) PlS[c] = 0.0f;

#pragma unroll 2
        for (int b = 0; b < NB; b++) {
            // ---- camera gray (scaled): a = 100 * mean(rgb) ----
            const float* cb = cam + (size_t)b * 3 * NPIX + n;
            float a = (cb[0] + cb[NPIX] + cb[2 * NPIX]) * (100.0f / 3.0f);

            // ---- label soft-argmax (beta = 500) ----
            const float* lbp = lab + (size_t)b * 4 * NPIX + n;
            float l0 = lbp[0];
            float l1 = lbp[NPIX];
            float l2 = lbp[2 * NPIX];
            float l3 = lbp[3 * NPIX];
            float m  = fmaxf(fmaxf(l0, l1), fmaxf(l2, l3));
            float e0 = __expf((l0 - m) * 500.0f);
            float e1 = __expf((l1 - m) * 500.0f);
            float e2 = __expf((l2 - m) * 500.0f);
            float e3 = __expf((l3 - m) * 500.0f);
            float esum = e0 + e1 + e2 + e3;   // >= 1, so +1e-12 is a no-op in fp32
            float labv = __fdividef(fmaf(3.0f, e3, fmaf(2.0f, e2, e1)), esum);

            // ---- label histogram: single non-saturated edge sigmoid (tanh) ----
            float u  = labv + 0.5f;
            float ce = rintf(u);                       // nearest edge 0..4
            float x  = (u - ce) * 500.0f;              // tanh half-argument
            float sg = fmaf(0.5f, tanh_fast(x), 0.5f); // sigmoid value
            int   ic = (int)ce;
#pragma unroll
            for (int c = 0; c < CBINS; c++) {
                float addv = (ic == c) ? sg : ((ic == c + 1) ? (1.0f - sg) : 0.0f);
                PlS[c] += addv;
            }

            // ---- camera: 17 edge tanh values ----
#pragma unroll
            for (int k = 0; k <= KBINS; k++) {
                T[k] += tanh_fast(fmaf(-6.25f, (float)k, a));
            }
        }

        // Pc[k] ~ (T[k] - T[k+1])   (x0.5 cancels under normalization)
#pragma unroll
        for (int k = 0; k < KBINS; k++) {
            float pc = T[k] - T[k + 1];
#pragma unroll
            for (int c = 0; c < CBINS; c++)
                acc_cl[k * CBINS + c] = fmaf(pc, PlS[c], acc_cl[k * CBINS + c]);
        }
#pragma unroll
        for (int c = 0; c < CBINS; c++) acc_l[c] += PlS[c];
    }

    // ---- block reduction: warp shuffle -> shared -> global atomics ----
    __shared__ float red[TPB / 32][NACC];
    unsigned lane = threadIdx.x & 31u;
    unsigned wrp  = threadIdx.x >> 5;

#pragma unroll
    for (int i = 0; i < KBINS * CBINS; i++) {
        float v = acc_cl[i];
        v += __shfl_down_sync(0xffffffffu, v, 16);
        v += __shfl_down_sync(0xffffffffu, v, 8);
        v += __shfl_down_sync(0xffffffffu, v, 4);
        v += __shfl_down_sync(0xffffffffu, v, 2);
        v += __shfl_down_sync(0xffffffffu, v, 1);
        if (lane == 0) red[wrp][i] = v;
    }
#pragma unroll
    for (int c = 0; c < CBINS; c++) {
        float v = acc_l[c];
        v += __shfl_down_sync(0xffffffffu, v, 16);
        v += __shfl_down_sync(0xffffffffu, v, 8);
        v += __shfl_down_sync(0xffffffffu, v, 4);
        v += __shfl_down_sync(0xffffffffu, v, 2);
        v += __shfl_down_sync(0xffffffffu, v, 1);
        if (lane == 0) red[wrp][KBINS * CBINS + c] = v;
    }
    __syncthreads();
    if (threadIdx.x < NACC) {
        float s = red[0][threadIdx.x] + red[1][threadIdx.x]
                + red[2][threadIdx.x] + red[3][threadIdx.x];
        atomicAdd(&g_acc[threadIdx.x], s);
    }
    __threadfence();   // publish g_acc contributions before taking a ticket
    __syncthreads();

    // ---- last-block finalize ----
    __shared__ unsigned int s_ticket;
    if (threadIdx.x == 0) s_ticket = atomicAdd(&g_ticket, 1u);
    __syncthreads();
    if (s_ticket != (unsigned)(GRID - 1)) return;

    if (threadIdx.x == 0) {
        __threadfence();  // acquire: see all blocks' atomics

        float pcl[KBINS * CBINS];
        float pl[CBINS];
        float scl = 0.0f, sl = 0.0f;
#pragma unroll
        for (int i = 0; i < KBINS * CBINS; i++) { pcl[i] = g_acc[i]; scl += pcl[i]; }
#pragma unroll
        for (int c = 0; c < CBINS; c++) { pl[c] = g_acc[KBINS * CBINS + c]; sl += pl[c]; }

        float inv_scl = 1.0f / scl;
        float inv_sl  = 1.0f / sl;

        float pc[KBINS];
#pragma unroll
        for (int k = 0; k < KBINS; k++) {
            float s = pcl[k * 4 + 0] + pcl[k * 4 + 1] + pcl[k * 4 + 2] + pcl[k * 4 + 3];
            pc[k] = s * inv_scl;   // row-marginal == normalized p_c (label mass 1/sample)
        }
#pragma unroll
        for (int c = 0; c < CBINS; c++) pl[c] *= inv_sl;

        float I = 0.0f, H = 0.0f;
#pragma unroll
        for (int k = 0; k < KBINS; k++) {
#pragma unroll
            for (int c = 0; c < CBINS; c++) {
                float p  = pcl[k * CBINS + c] * inv_scl;
                float lp = logf(p + 1e-7f);
                float lo = logf(pc[k] * pl[c] + 1e-7f);
                H -= p * lp;
                I += p * (lp - lo);
            }
        }
        float nid = 1.0f - I / H;
        out[0] = (nid - 0.95f) * 20.0f;

        // reset for next graph replay (deterministic across launches)
#pragma unroll
        for (int i = 0; i < NACC; i++) g_acc[i] = 0.0f;
        __threadfence();
        atomicExch(&g_ticket, 0u);
    }
}

extern "C" void kernel_launch(void* const* d_in, const int* in_sizes, int n_in,
                              void* d_out, int out_size)
{
    const float* cam = (const float*)d_in[0];   // (8,3,512,1024) fp32
    const float* lab = (const float*)d_in[1];   // (8,4,512,1024) fp32
    float* out = (float*)d_out;

    nid_kernel<<<GRID, TPB>>>(cam, lab, out);
}

// round 10
// speedup vs baseline: 1.0537x; 1.0537x over previous
#include <cuda_runtime.h>
#include <cuda_fp16.h>
#include <math.h>

#define NPIX  (512*1024)
#define NB    8
#define KBINS 16
#define CBINS 4
#define NACC  (KBINS*CBINS + CBINS)   // 64 p_cl + 4 p_l = 68
#define TPB   128
#define GRID  592                     // 148 SMs * 4 blocks (one wave at 128 regs)

__device__ float g_acc[NACC];         // zero at module load; reset by last block each run
__device__ unsigned int g_ticket;     // zero at module load; reset by last block each run

__device__ __forceinline__ __half2 tanh_h2(__half2 x) {
    unsigned r;
    unsigned xi = *reinterpret_cast<unsigned*>(&x);
    asm("tanh.approx.f16x2 %0, %1;" : "=r"(r) : "r"(xi));
    return *reinterpret_cast<__half2*>(&r);
}

__global__ void __launch_bounds__(TPB, 4)
nid_kernel(const float* __restrict__ cam, const float* __restrict__ lab,
           float* __restrict__ out)
{
    float acc_cl[KBINS * CBINS];
    float acc_l[CBINS];
#pragma unroll
    for (int i = 0; i < KBINS * CBINS; i++) acc_cl[i] = 0.0f;
#pragma unroll
    for (int c = 0; c < CBINS; c++) acc_l[c] = 0.0f;

    const __half2 h2zero = __floats2half2_rn(0.0f, 0.0f);
    const int stride = GRID * TPB;
#pragma unroll 1
    for (int n = blockIdx.x * TPB + threadIdx.x; n < NPIX; n += stride) {
        // T2[k]: half2 accumulator; lane0 sums even batches, lane1 odd batches.
        // T[k] = sum_b tanh(100*gray_b - 6.25*k); +1/*0.5 of sigmoid cancel in
        // differences / normalization.
        __half2 T2[KBINS + 1];
        float PlS[CBINS];
#pragma unroll
        for (int k = 0; k <= KBINS; k++) T2[k] = h2zero;
#pragma unroll
        for (int c = 0; c < CBINS; c++) PlS[c] = 0.0f;

#pragma unroll
        for (int p = 0; p < NB / 2; p++) {
            const int b0 = 2 * p, b1 = 2 * p + 1;

            // ---- camera gray (scaled): a = 100 * mean(rgb) ----
            const float* c0 = cam + (size_t)b0 * 3 * NPIX + n;
            const float* c1 = cam + (size_t)b1 * 3 * NPIX + n;
            float a0 = (c0[0] + c0[NPIX] + c0[2 * NPIX]) * (100.0f / 3.0f);
            float a1 = (c1[0] + c1[NPIX] + c1[2 * NPIX]) * (100.0f / 3.0f);

            // ---- label soft-argmax (beta = 500), fp32, batch b0 ----
            const float* lp0 = lab + (size_t)b0 * 4 * NPIX + n;
            float p00 = lp0[0], p01 = lp0[NPIX], p02 = lp0[2 * NPIX], p03 = lp0[3 * NPIX];
            float m0  = fmaxf(fmaxf(p00, p01), fmaxf(p02, p03));
            float e00 = __expf((p00 - m0) * 500.0f);
            float e01 = __expf((p01 - m0) * 500.0f);
            float e02 = __expf((p02 - m0) * 500.0f);
            float e03 = __expf((p03 - m0) * 500.0f);
            float es0 = e00 + e01 + e02 + e03;   // >= 1, +1e-12 is an fp32 no-op
            float lv0 = __fdividef(fmaf(3.0f, e03, fmaf(2.0f, e02, e01)), es0);

            // ---- batch b1 ----
            const float* lp1 = lab + (size_t)b1 * 4 * NPIX + n;
            float p10 = lp1[0], p11 = lp1[NPIX], p12 = lp1[2 * NPIX], p13 = lp1[3 * NPIX];
            float m1  = fmaxf(fmaxf(p10, p11), fmaxf(p12, p13));
            float e10 = __expf((p10 - m1) * 500.0f);
            float e11 = __expf((p11 - m1) * 500.0f);
            float e12 = __expf((p12 - m1) * 500.0f);
            float e13 = __expf((p13 - m1) * 500.0f);
            float es1 = e10 + e11 + e12 + e13;
            float lv1 = __fdividef(fmaf(3.0f, e13, fmaf(2.0f, e12, e11)), es1);

            // ---- label-edge sigmoid: one packed tanh for both batches ----
            float u0 = lv0 + 0.5f, u1 = lv1 + 0.5f;
            float ce0 = rintf(u0), ce1 = rintf(u1);
            float x0 = (u0 - ce0) * 500.0f;           // tanh half-argument
            float x1 = (u1 - ce1) * 500.0f;
            __half2 ht = tanh_h2(__floats2half2_rn(x0, x1));
            float2 tf = __half22float2(ht);
            float sg0 = fmaf(0.5f, tf.x, 0.5f);
            float sg1 = fmaf(0.5f, tf.y, 0.5f);
            int ic0 = (int)ce0, ic1 = (int)ce1;
#pragma unroll
            for (int c = 0; c < CBINS; c++) {
                float add0 = (ic0 == c) ? sg0 : ((ic0 == c + 1) ? (1.0f - sg0) : 0.0f);
                float add1 = (ic1 == c) ? sg1 : ((ic1 == c + 1) ? (1.0f - sg1) : 0.0f);
                PlS[c] += add0 + add1;
            }

            // ---- camera: 17 edges, one packed tanh per edge for both batches ----
#pragma unroll
            for (int k = 0; k <= KBINS; k++) {
                float arg0 = fmaf(-6.25f, (float)k, a0);
                float arg1 = fmaf(-6.25f, (float)k, a1);
                __half2 h = tanh_h2(__floats2half2_rn(arg0, arg1));
                T2[k] = __hadd2(T2[k], h);
            }
        }

        // Pc[k] ~ (T[k] - T[k+1]); x0.5 cancels under normalization
        float Tprev;
        {
            float2 f = __half22float2(T2[0]);
            Tprev = f.x + f.y;
        }
#pragma unroll
        for (int k = 0; k < KBINS; k++) {
            float2 f = __half22float2(T2[k + 1]);
            float Tnext = f.x + f.y;
            float pc = Tprev - Tnext;
            Tprev = Tnext;
#pragma unroll
            for (int c = 0; c < CBINS; c++)
                acc_cl[k * CBINS + c] = fmaf(pc, PlS[c], acc_cl[k * CBINS + c]);
        }
#pragma unroll
        for (int c = 0; c < CBINS; c++) acc_l[c] += PlS[c];
    }

    // ---- block reduction: warp shuffle -> shared -> global atomics ----
    __shared__ float red[TPB / 32][NACC];
    unsigned lane = threadIdx.x & 31u;
    unsigned wrp  = threadIdx.x >> 5;

#pragma unroll
    for (int i = 0; i < KBINS * CBINS; i++) {
        float v = acc_cl[i];
        v += __shfl_down_sync(0xffffffffu, v, 16);
        v += __shfl_down_sync(0xffffffffu, v, 8);
        v += __shfl_down_sync(0xffffffffu, v, 4);
        v += __shfl_down_sync(0xffffffffu, v, 2);
        v += __shfl_down_sync(0xffffffffu, v, 1);
        if (lane == 0) red[wrp][i] = v;
    }
#pragma unroll
    for (int c = 0; c < CBINS; c++) {
        float v = acc_l[c];
        v += __shfl_down_sync(0xffffffffu, v, 16);
        v += __shfl_down_sync(0xffffffffu, v, 8);
        v += __shfl_down_sync(0xffffffffu, v, 4);
        v += __shfl_down_sync(0xffffffffu, v, 2);
        v += __shfl_down_sync(0xffffffffu, v, 1);
        if (lane == 0) red[wrp][KBINS * CBINS + c] = v;
    }
    __syncthreads();
    if (threadIdx.x < NACC) {
        float s = red[0][threadIdx.x] + red[1][threadIdx.x]
                + red[2][threadIdx.x] + red[3][threadIdx.x];
        atomicAdd(&g_acc[threadIdx.x], s);
    }
    __threadfence();   // publish g_acc contributions before taking a ticket
    __syncthreads();

    // ---- last-block finalize ----
    __shared__ unsigned int s_ticket;
    if (threadIdx.x == 0) s_ticket = atomicAdd(&g_ticket, 1u);
    __syncthreads();
    if (s_ticket != (unsigned)(GRID - 1)) return;

    if (threadIdx.x == 0) {
        __threadfence();  // acquire: see all blocks' atomics

        float pcl[KBINS * CBINS];
        float pl[CBINS];
        float scl = 0.0f, sl = 0.0f;
#pragma unroll
        for (int i = 0; i < KBINS * CBINS; i++) { pcl[i] = g_acc[i]; scl += pcl[i]; }
#pragma unroll
        for (int c = 0; c < CBINS; c++) { pl[c] = g_acc[KBINS * CBINS + c]; sl += pl[c]; }

        float inv_scl = 1.0f / scl;
        float inv_sl  = 1.0f / sl;

        float pc[KBINS];
#pragma unroll
        for (int k = 0; k < KBINS; k++) {
            float s = pcl[k * 4 + 0] + pcl[k * 4 + 1] + pcl[k * 4 + 2] + pcl[k * 4 + 3];
            pc[k] = s * inv_scl;   // row-marginal == normalized p_c
        }
#pragma unroll
        for (int c = 0; c < CBINS; c++) pl[c] *= inv_sl;

        float I = 0.0f, H = 0.0f;
#pragma unroll
        for (int k = 0; k < KBINS; k++) {
#pragma unroll
            for (int c = 0; c < CBINS; c++) {
                float p  = pcl[k * CBINS + c] * inv_scl;
                float lp = logf(p + 1e-7f);
                float lo = logf(pc[k] * pl[c] + 1e-7f);
                H -= p * lp;
                I += p * (lp - lo);
            }
        }
        float nid = 1.0f - I / H;
        out[0] = (nid - 0.95f) * 20.0f;

        // reset for next graph replay (deterministic across launches)
#pragma unroll
        for (int i = 0; i < NACC; i++) g_acc[i] = 0.0f;
        __threadfence();
        atomicExch(&g_ticket, 0u);
    }
}

extern "C" void kernel_launch(void* const* d_in, const int* in_sizes, int n_in,
                              void* d_out, int out_size)
{
    const float* cam = (const float*)d_in[0];   // (8,3,512,1024) fp32
    const float* lab = (const float*)d_in[1];   // (8,4,512,1024) fp32
    float* out = (float*)d_out;

    nid_kernel<<<GRID, TPB>>>(cam, lab, out);
}